// round 9
// baseline (speedup 1.0000x reference)
#include <cuda_runtime.h>
#include <math.h>

#define BB 4
#define NN 2048
#define NBINS 10
#define NP 5
#define BN (BB*NN)
#define NTILES 8     // gt-row tiles of 256 rows
#define MSPLIT 16    // pred-col tiles of 128 cols
#define FINF 3.0e38f

// ---------------- scratch (device globals; no allocations allowed) -----------
__device__ float4 g_predCP[BN*4];
__device__ float4 g_gtCP[BN*4];
__device__ float g_cd[BN], g_ca[BN], g_off[BN], g_sbce[BN];
__device__ float g_pm1[MSPLIT][BN], g_pm2[MSPLIT][BN];
__device__ int   g_pi1[MSPLIT][BN], g_pi2[MSPLIT][BN];
__device__ float g_colmin[NTILES][BN];
__device__ float g_part[32][8];   // per-block partials: cd,ca,off,g2p,adds,succ,sbce
__device__ int   g_ctr;           // zero-initialized; returns to 0 every call

__device__ __forceinline__ float softplusf(float x){
    return log1pf(expf(-fabsf(x))) + fmaxf(x, 0.0f);
}

// ---------------- Kernel A: per-point setup + cheap losses -------------------
__global__ void kA(const float* __restrict__ gd_, const float* __restrict__ ad_,
                   const float* __restrict__ oh_, const float* __restrict__ pp_,
                   const float* __restrict__ bsh_, const float* __restrict__ dl_,
                   const float* __restrict__ ol_, const float* __restrict__ succ_,
                   const float* __restrict__ al_, const float* __restrict__ bv,
                   const float* __restrict__ bw, const float* __restrict__ cpt,
                   const float* __restrict__ scpt)
{
    int idx = blockIdx.x*blockDim.x + threadIdx.x;
    if (idx >= BN) return;

    const float gd0=gd_[idx*3+0], gd1=gd_[idx*3+1], gd2=gd_[idx*3+2];
    const float ad0=ad_[idx*3+0], ad1=ad_[idx*3+1], ad2=ad_[idx*3+2];
    const float pp0=pp_[idx*3+0], pp1=pp_[idx*3+1], pp2=pp_[idx*3+2];
    const float dl0=dl_[idx*3+0], dl1=dl_[idx*3+1], dl2=dl_[idx*3+2];
    const float al0=al_[idx*3+0], al1=al_[idx*3+1], al2=al_[idx*3+2];
    const float succ = succ_[idx];

    // first-occurrence argmax (matches jnp.argmax)
    float oh[NBINS], ol[NBINS];
    float bp=-FINF, bg=-FINF; int ip=0, ig=0;
    #pragma unroll
    for (int i=0;i<NBINS;i++){
        oh[i]=oh_[idx*NBINS+i]; ol[i]=ol_[idx*NBINS+i];
        if (oh[i] > bp){bp=oh[i]; ip=i;}
        if (ol[i] > bg){bg=ol[i]; ig=i;}
    }
    const float tp = bv[ip], tg = bv[ig];

    // pred frame
    const float pc0 = ad1*gd2 - ad2*gd1;
    const float pc1 = ad2*gd0 - ad0*gd2;
    const float pc2 = ad0*gd1 - ad1*gd0;
    const float pt0 = pp0 + 0.5f*tp*gd0, pt1 = pp1 + 0.5f*tp*gd1, pt2 = pp2 + 0.5f*tp*gd2;
    // gt frame
    const float gc0 = al1*dl2 - al2*dl1;
    const float gc1 = al2*dl0 - al0*dl2;
    const float gc2 = al0*dl1 - al1*dl0;
    const float gt0 = pp0 + 0.5f*tg*dl0, gt1 = pp1 + 0.5f*tg*dl1, gt2 = pp2 + 0.5f*tg*dl2;

    float vp[16], vg[16];
    float pn2=0.f, gn2=0.f;
    #pragma unroll
    for (int p=0;p<NP;p++){
        const float cx=cpt[p*3+0], cy=cpt[p*3+1], cz=cpt[p*3+2];
        const float px = cx*gd0 + cy*pc0 + cz*ad0 + pt0;
        const float py = cx*gd1 + cy*pc1 + cz*ad1 + pt1;
        const float pz = cx*gd2 + cy*pc2 + cz*ad2 + pt2;
        const float gx = cx*dl0 + cy*gc0 + cz*al0 + gt0;
        const float gy = cx*dl1 + cy*gc1 + cz*al1 + gt1;
        const float gz = cx*dl2 + cy*gc2 + cz*al2 + gt2;
        vp[p*3+0]=px; vp[p*3+1]=py; vp[p*3+2]=pz;
        vg[p*3+0]=gx; vg[p*3+1]=gy; vg[p*3+2]=gz;
        pn2 += px*px+py*py+pz*pz;
        gn2 += gx*gx+gy*gy+gz*gz;
    }
    vp[15]=pn2; vg[15]=gn2;

    #pragma unroll
    for (int q=0;q<4;q++){
        g_predCP[idx*4+q] = make_float4(vp[q*4+0], vp[q*4+1], vp[q*4+2], vp[q*4+3]);
        g_gtCP[idx*4+q]   = make_float4(vg[q*4+0], vg[q*4+1], vg[q*4+2], vg[q*4+3]);
    }

    const float cd = (1.0f - (dl0*gd0+dl1*gd1+dl2*gd2))*succ;
    const float proj = gd0*al0+gd1*al1+gd2*al2;
    const float o0=al0-proj*gd0, o1=al1-proj*gd1, o2=al2-proj*gd2;
    const float nrm = sqrtf(o0*o0+o1*o1+o2*o2);
    const float inv = 1.0f/fmaxf(nrm,1e-12f);
    const float ca = (1.0f - (o0*ad0+o1*ad1+o2*ad2)*inv)*succ;
    float off=0.f;
    #pragma unroll
    for (int i=0;i<NBINS;i++){
        const float bce = ol[i]*softplusf(-oh[i]) + (1.0f-ol[i])*softplusf(oh[i]);
        off += bw[i]*bce;
    }
    off = off*(1.0f/NBINS)*succ;
    const float h = bsh_[idx];
    const float sbce = succ*softplusf(-h) + (1.0f-succ)*softplusf(h);

    g_cd[idx]=cd; g_ca[idx]=ca; g_off[idx]=off; g_sbce[idx]=sbce;
}

// ---------------- Kernel B: tiled NxN reductions ------------------------------
// Each thread owns 2 gt rows (row, row+128). Sym control points are the
// permutation [0,1,3,2,4] of gt control points: dotS reuses 3 of 5 segment dots
// and the sym squared-norm equals the gt squared-norm. Column-min over the tile
// gives the pred->gt "best" (masked rows -> FINF, finite) for free.
__global__ void __launch_bounds__(128) kB(const float* __restrict__ succ_)
{
    __shared__ float4 s4PR[128*4];       // pred tile, 8 KB
    __shared__ float  scand[128][65];    // half-tile candidates, 33.3 KB
    __shared__ float  scolpart[128];

    const int ntile = blockIdx.x;    // 0..7  (gt rows base = ntile*256)
    const int b     = blockIdx.y;    // 0..3
    const int split = blockIdx.z;    // 0..15 (pred cols base = split*128)
    const int tid   = threadIdx.x;   // 0..127
    const int row0  = ntile*256 + tid;
    const int gA    = b*NN + row0;
    const int gB    = gA + 128;
    const int mbase = split*128;

    float ra[16], rb[16];
    #pragma unroll
    for (int q=0;q<4;q++){
        const float4 u = g_gtCP[gA*4+q];
        const float4 v = g_gtCP[gB*4+q];
        ra[q*4+0]=u.x; ra[q*4+1]=u.y; ra[q*4+2]=u.z; ra[q*4+3]=u.w;
        rb[q*4+0]=v.x; rb[q*4+1]=v.y; rb[q*4+2]=v.z; rb[q*4+3]=v.w;
    }
    const bool posA = succ_[gA] > 0.5f;
    const bool posB = succ_[gB] > 0.5f;

    {
        const int src4 = (b*NN + mbase)*4;
        #pragma unroll
        for (int i=tid;i<128*4;i+=128) s4PR[i]=g_predCP[src4+i];
    }
    __syncthreads();

    float m1a=FINF,m2a=FINF, m1b=FINF,m2b=FINF;
    int i1a=0,i2a=0, i1b=0,i2b=0;

    #pragma unroll
    for (int h=0;h<2;h++){
        const int jbase = h*64;
        #pragma unroll 4
        for (int j=0;j<64;j++){
            const int jj = jbase + j;
            const float4 c0=s4PR[jj*4+0], c1=s4PR[jj*4+1], c2=s4PR[jj*4+2], c3=s4PR[jj*4+3];

            // ---- row A ----
            float A0 = ra[0]*c0.x + ra[1]*c0.y + ra[2]*c0.z;
            float A1 = ra[3]*c0.w + ra[4]*c1.x + ra[5]*c1.y;
            float A2 = ra[6]*c1.z + ra[7]*c1.w + ra[8]*c2.x;
            float A3 = ra[9]*c2.y + ra[10]*c2.z + ra[11]*c2.w;
            float A4 = ra[12]*c3.x + ra[13]*c3.y + ra[14]*c3.z;
            float P2 = ra[9]*c1.z + ra[10]*c1.w + ra[11]*c2.x;   // gt seg3 . pred seg2
            float P3 = ra[6]*c2.y + ra[7]*c2.z + ra[8]*c2.w;     // gt seg2 . pred seg3
            float s014 = A0 + A1 + A4;
            float dotG = s014 + A2 + A3;
            float dotS = s014 + P2 + P3;
            float base = ra[15] + c3.w;
            float dgA0 = fmaxf(fmaf(-2.0f, dotG, base), 0.0f);
            float dgB0 = fmaxf(fmaf(-2.0f, dotS, base), 0.0f);
            if (dgA0 < m1a){ m1a=dgA0; i1a=mbase+jj; }
            if (dgB0 < m2a){ m2a=dgB0; i2a=mbase+jj; }

            // ---- row B ----
            float C0 = rb[0]*c0.x + rb[1]*c0.y + rb[2]*c0.z;
            float C1 = rb[3]*c0.w + rb[4]*c1.x + rb[5]*c1.y;
            float C2 = rb[6]*c1.z + rb[7]*c1.w + rb[8]*c2.x;
            float C3 = rb[9]*c2.y + rb[10]*c2.z + rb[11]*c2.w;
            float C4 = rb[12]*c3.x + rb[13]*c3.y + rb[14]*c3.z;
            float Q2 = rb[9]*c1.z + rb[10]*c1.w + rb[11]*c2.x;
            float Q3 = rb[6]*c2.y + rb[7]*c2.z + rb[8]*c2.w;
            float t014 = C0 + C1 + C4;
            float dotG2 = t014 + C2 + C3;
            float dotS2 = t014 + Q2 + Q3;
            float base2 = rb[15] + c3.w;
            float dgA1 = fmaxf(fmaf(-2.0f, dotG2, base2), 0.0f);
            float dgB1 = fmaxf(fmaf(-2.0f, dotS2, base2), 0.0f);
            if (dgA1 < m1b){ m1b=dgA1; i1b=mbase+jj; }
            if (dgB1 < m2b){ m2b=dgB1; i2b=mbase+jj; }

            const float candA = posA ? fminf(dgA0,dgB0) : FINF;
            const float candB = posB ? fminf(dgA1,dgB1) : FINF;
            scand[tid][j] = fminf(candA, candB);
        }
        __syncthreads();

        // column-min: 2 threads per column over 128 thread-rows
        const int col  = tid & 63;
        const int half = tid >> 6;
        float cm = scand[half*64][col];
        #pragma unroll 8
        for (int i=1;i<64;i++) cm = fminf(cm, scand[half*64+i][col]);
        scolpart[tid] = cm;
        __syncthreads();
        if (tid < 64)
            g_colmin[ntile][b*NN + mbase + jbase + tid] =
                fminf(scolpart[tid], scolpart[tid+64]);
        __syncthreads();
    }

    g_pm1[split][gA]=m1a; g_pi1[split][gA]=i1a;
    g_pm2[split][gA]=m2a; g_pi2[split][gA]=i2a;
    g_pm1[split][gB]=m1b; g_pi1[split][gB]=i1b;
    g_pm2[split][gB]=m2b; g_pi2[split][gB]=i2b;
}

// ---------------- Kernel C: epilogue + fused last-block final merge -----------
__global__ void kC(const float* __restrict__ bsp, const float* __restrict__ succ_,
                   float* __restrict__ out)
{
    __shared__ float red[256];
    __shared__ bool  s_last;
    const int tid = threadIdx.x;
    const int g   = blockIdx.x*256 + tid;   // 32 blocks x 256 = 8192
    const int b   = g >> 11;

    const float succ = succ_[g];
    const float cd = g_cd[g], ca = g_ca[g], off = g_off[g], sbce = g_sbce[g];

    // pred->gt best: merge NTILES column partials (min, order-free); always finite
    float best = g_colmin[0][g];
    #pragma unroll
    for (int t=1;t<NTILES;t++) best = fminf(best, g_colmin[t][g]);
    const float adds = bsp[g]*sqrtf(best);   // gate applied per-batch at merge

    // gt->pred: ordered merge of MSPLIT partials (first-occurrence argmin)
    float m1=g_pm1[0][g]; int i1=g_pi1[0][g];
    float m2=g_pm2[0][g]; int i2=g_pi2[0][g];
    #pragma unroll
    for (int s=1;s<MSPLIT;s++){
        const float a=g_pm1[s][g]; if (a<m1){m1=a;i1=g_pi1[s][g];}
        const float c=g_pm2[s][g]; if (c<m2){m2=c;i2=g_pi2[s][g];}
    }
    const int idcs = (m2<m1)? i2 : i1;
    const float conf = bsp[b*NN+idcs];
    const float g2p = conf * fminf(m1,m2) * succ;

    float vals[7] = {cd, ca, off, g2p, adds, succ, sbce};
    #pragma unroll
    for (int q=0;q<7;q++){
        red[tid]=vals[q]; __syncthreads();
        for (int s=128;s>0;s>>=1){ if(tid<s) red[tid]+=red[tid+s]; __syncthreads(); }
        if (tid==0) g_part[blockIdx.x][q]=red[0];
        __syncthreads();
    }

    // ---- last block performs the deterministic final merge ----
    if (tid==0){
        __threadfence();
        const int v = atomicAdd(&g_ctr, 1);
        s_last = (v == 31);
    }
    __syncthreads();
    if (s_last && tid==0){
        __threadfence();     // make all g_part writes visible
        float tdir=0.f,tapp=0.f,toff=0.f,tg2p=0.f,tadds=0.f,tsb=0.f;
        for (int bb=0;bb<BB;bb++){
            float s[7]={0,0,0,0,0,0,0};
            for (int k=0;k<8;k++){            // 8 blocks per batch, fixed order
                #pragma unroll
                for (int q=0;q<7;q++) s[q]+=g_part[bb*8+k][q];
            }
            const float piv  = fmaxf(s[5],1.0f);
            const float gate = fminf(s[5],1.0f);
            tdir += s[0]/piv; tapp += s[1]/piv; toff += s[2]/piv;
            tg2p += s[3]/piv; tadds += gate*s[4]; tsb += s[6];
        }
        out[0] = tdir/(float)BB + tsb/(float)BN + toff/(float)BB + tapp/(float)BB
               + 10.0f*(tadds/(float)BN) + tg2p/(float)BB;
        g_ctr = 0;           // reset for next call / graph replay
    }
}

// ---------------- launcher ---------------------------------------------------
extern "C" void kernel_launch(void* const* d_in, const int* in_sizes, int n_in,
                              void* d_out, int out_size)
{
    const float* gd   = (const float*)d_in[0];
    const float* ad   = (const float*)d_in[1];
    const float* oh   = (const float*)d_in[2];
    const float* pp   = (const float*)d_in[3];
    const float* bsp  = (const float*)d_in[4];
    const float* bsh  = (const float*)d_in[5];
    const float* dl   = (const float*)d_in[6];
    const float* ol   = (const float*)d_in[7];
    const float* succ = (const float*)d_in[8];
    const float* al   = (const float*)d_in[9];
    const float* bv   = (const float*)d_in[10];
    const float* bw   = (const float*)d_in[11];
    const float* cpt  = (const float*)d_in[12];
    const float* scpt = (const float*)d_in[13];
    float* out = (float*)d_out;

    kA<<<BN/128, 128>>>(gd, ad, oh, pp, bsh, dl, ol, succ, al, bv, bw, cpt, scpt);
    kB<<<dim3(NTILES, BB, MSPLIT), 128>>>(succ);
    kC<<<32, 256>>>(bsp, succ, out);
}

// round 10
// speedup vs baseline: 1.5783x; 1.5783x over previous
#include <cuda_runtime.h>
#include <math.h>

#define BB 4
#define NN 2048
#define NBINS 10
#define NP 5
#define BN (BB*NN)
#define NTILES 8     // gt-row tiles of 256 rows
#define MSPLIT 16    // pred-col tiles of 128 cols
#define FINF 3.0e38f

// ---------------- scratch (device globals; no allocations allowed) -----------
__device__ float4 g_predCP[BN*4];
__device__ float4 g_gtCP[BN*4];
__device__ float g_cd[BN], g_ca[BN], g_off[BN], g_sbce[BN];
__device__ float g_pm1[MSPLIT][BN], g_pm2[MSPLIT][BN];
__device__ int   g_pi1[MSPLIT][BN], g_pi2[MSPLIT][BN];
__device__ float g_colmin[NTILES][BN];
__device__ float g_part[32][8];   // per-block partials: cd,ca,off,g2p,adds,succ,sbce

__device__ __forceinline__ float softplusf(float x){
    return log1pf(expf(-fabsf(x))) + fmaxf(x, 0.0f);
}

// ---------------- Kernel A: per-point setup + cheap losses -------------------
__global__ void kA(const float* __restrict__ gd_, const float* __restrict__ ad_,
                   const float* __restrict__ oh_, const float* __restrict__ pp_,
                   const float* __restrict__ bsh_, const float* __restrict__ dl_,
                   const float* __restrict__ ol_, const float* __restrict__ succ_,
                   const float* __restrict__ al_, const float* __restrict__ bv,
                   const float* __restrict__ bw, const float* __restrict__ cpt,
                   const float* __restrict__ scpt)
{
    int idx = blockIdx.x*blockDim.x + threadIdx.x;
    if (idx >= BN) return;

    const float gd0=gd_[idx*3+0], gd1=gd_[idx*3+1], gd2=gd_[idx*3+2];
    const float ad0=ad_[idx*3+0], ad1=ad_[idx*3+1], ad2=ad_[idx*3+2];
    const float pp0=pp_[idx*3+0], pp1=pp_[idx*3+1], pp2=pp_[idx*3+2];
    const float dl0=dl_[idx*3+0], dl1=dl_[idx*3+1], dl2=dl_[idx*3+2];
    const float al0=al_[idx*3+0], al1=al_[idx*3+1], al2=al_[idx*3+2];
    const float succ = succ_[idx];

    // first-occurrence argmax (matches jnp.argmax)
    float oh[NBINS], ol[NBINS];
    float bp=-FINF, bg=-FINF; int ip=0, ig=0;
    #pragma unroll
    for (int i=0;i<NBINS;i++){
        oh[i]=oh_[idx*NBINS+i]; ol[i]=ol_[idx*NBINS+i];
        if (oh[i] > bp){bp=oh[i]; ip=i;}
        if (ol[i] > bg){bg=ol[i]; ig=i;}
    }
    const float tp = bv[ip], tg = bv[ig];

    // pred frame
    const float pc0 = ad1*gd2 - ad2*gd1;
    const float pc1 = ad2*gd0 - ad0*gd2;
    const float pc2 = ad0*gd1 - ad1*gd0;
    const float pt0 = pp0 + 0.5f*tp*gd0, pt1 = pp1 + 0.5f*tp*gd1, pt2 = pp2 + 0.5f*tp*gd2;
    // gt frame
    const float gc0 = al1*dl2 - al2*dl1;
    const float gc1 = al2*dl0 - al0*dl2;
    const float gc2 = al0*dl1 - al1*dl0;
    const float gt0 = pp0 + 0.5f*tg*dl0, gt1 = pp1 + 0.5f*tg*dl1, gt2 = pp2 + 0.5f*tg*dl2;

    float vp[16], vg[16];
    float pn2=0.f, gn2=0.f;
    #pragma unroll
    for (int p=0;p<NP;p++){
        const float cx=cpt[p*3+0], cy=cpt[p*3+1], cz=cpt[p*3+2];
        const float px = cx*gd0 + cy*pc0 + cz*ad0 + pt0;
        const float py = cx*gd1 + cy*pc1 + cz*ad1 + pt1;
        const float pz = cx*gd2 + cy*pc2 + cz*ad2 + pt2;
        const float gx = cx*dl0 + cy*gc0 + cz*al0 + gt0;
        const float gy = cx*dl1 + cy*gc1 + cz*al1 + gt1;
        const float gz = cx*dl2 + cy*gc2 + cz*al2 + gt2;
        vp[p*3+0]=px; vp[p*3+1]=py; vp[p*3+2]=pz;
        vg[p*3+0]=gx; vg[p*3+1]=gy; vg[p*3+2]=gz;
        pn2 += px*px+py*py+pz*pz;
        gn2 += gx*gx+gy*gy+gz*gz;
    }
    vp[15]=pn2; vg[15]=gn2;

    #pragma unroll
    for (int q=0;q<4;q++){
        g_predCP[idx*4+q] = make_float4(vp[q*4+0], vp[q*4+1], vp[q*4+2], vp[q*4+3]);
        g_gtCP[idx*4+q]   = make_float4(vg[q*4+0], vg[q*4+1], vg[q*4+2], vg[q*4+3]);
    }

    const float cd = (1.0f - (dl0*gd0+dl1*gd1+dl2*gd2))*succ;
    const float proj = gd0*al0+gd1*al1+gd2*al2;
    const float o0=al0-proj*gd0, o1=al1-proj*gd1, o2=al2-proj*gd2;
    const float nrm = sqrtf(o0*o0+o1*o1+o2*o2);
    const float inv = 1.0f/fmaxf(nrm,1e-12f);
    const float ca = (1.0f - (o0*ad0+o1*ad1+o2*ad2)*inv)*succ;
    float off=0.f;
    #pragma unroll
    for (int i=0;i<NBINS;i++){
        const float bce = ol[i]*softplusf(-oh[i]) + (1.0f-ol[i])*softplusf(oh[i]);
        off += bw[i]*bce;
    }
    off = off*(1.0f/NBINS)*succ;
    const float h = bsh_[idx];
    const float sbce = succ*softplusf(-h) + (1.0f-succ)*softplusf(h);

    g_cd[idx]=cd; g_ca[idx]=ca; g_off[idx]=off; g_sbce[idx]=sbce;
}

// ---------------- Kernel B: tiled NxN reductions ------------------------------
// Each thread owns 2 gt rows (row, row+128). Sym control points are the
// permutation [0,1,3,2,4] of gt control points: dotS reuses 3 of 5 segment dots
// and the sym squared-norm equals the gt squared-norm. Column-min over the tile
// gives the pred->gt "best" (masked rows -> FINF, finite) for free.
__global__ void __launch_bounds__(128) kB(const float* __restrict__ succ_)
{
    __shared__ float4 s4PR[128*4];       // pred tile, 8 KB
    __shared__ float  scand[128][65];    // half-tile candidates, 33.3 KB
    __shared__ float  scolpart[128];

    const int ntile = blockIdx.x;    // 0..7  (gt rows base = ntile*256)
    const int b     = blockIdx.y;    // 0..3
    const int split = blockIdx.z;    // 0..15 (pred cols base = split*128)
    const int tid   = threadIdx.x;   // 0..127
    const int row0  = ntile*256 + tid;
    const int gA    = b*NN + row0;
    const int gB    = gA + 128;
    const int mbase = split*128;

    float ra[16], rb[16];
    #pragma unroll
    for (int q=0;q<4;q++){
        const float4 u = g_gtCP[gA*4+q];
        const float4 v = g_gtCP[gB*4+q];
        ra[q*4+0]=u.x; ra[q*4+1]=u.y; ra[q*4+2]=u.z; ra[q*4+3]=u.w;
        rb[q*4+0]=v.x; rb[q*4+1]=v.y; rb[q*4+2]=v.z; rb[q*4+3]=v.w;
    }
    const bool posA = succ_[gA] > 0.5f;
    const bool posB = succ_[gB] > 0.5f;

    {
        const int src4 = (b*NN + mbase)*4;
        #pragma unroll
        for (int i=tid;i<128*4;i+=128) s4PR[i]=g_predCP[src4+i];
    }
    __syncthreads();

    float m1a=FINF,m2a=FINF, m1b=FINF,m2b=FINF;
    int i1a=0,i2a=0, i1b=0,i2b=0;

    #pragma unroll
    for (int h=0;h<2;h++){
        const int jbase = h*64;
        #pragma unroll 4
        for (int j=0;j<64;j++){
            const int jj = jbase + j;
            const float4 c0=s4PR[jj*4+0], c1=s4PR[jj*4+1], c2=s4PR[jj*4+2], c3=s4PR[jj*4+3];

            // ---- row A ----
            float A0 = ra[0]*c0.x + ra[1]*c0.y + ra[2]*c0.z;
            float A1 = ra[3]*c0.w + ra[4]*c1.x + ra[5]*c1.y;
            float A2 = ra[6]*c1.z + ra[7]*c1.w + ra[8]*c2.x;
            float A3 = ra[9]*c2.y + ra[10]*c2.z + ra[11]*c2.w;
            float A4 = ra[12]*c3.x + ra[13]*c3.y + ra[14]*c3.z;
            float P2 = ra[9]*c1.z + ra[10]*c1.w + ra[11]*c2.x;   // gt seg3 . pred seg2
            float P3 = ra[6]*c2.y + ra[7]*c2.z + ra[8]*c2.w;     // gt seg2 . pred seg3
            float s014 = A0 + A1 + A4;
            float dotG = s014 + A2 + A3;
            float dotS = s014 + P2 + P3;
            float base = ra[15] + c3.w;
            float dgA0 = fmaxf(fmaf(-2.0f, dotG, base), 0.0f);
            float dgB0 = fmaxf(fmaf(-2.0f, dotS, base), 0.0f);
            if (dgA0 < m1a){ m1a=dgA0; i1a=mbase+jj; }
            if (dgB0 < m2a){ m2a=dgB0; i2a=mbase+jj; }

            // ---- row B ----
            float C0 = rb[0]*c0.x + rb[1]*c0.y + rb[2]*c0.z;
            float C1 = rb[3]*c0.w + rb[4]*c1.x + rb[5]*c1.y;
            float C2 = rb[6]*c1.z + rb[7]*c1.w + rb[8]*c2.x;
            float C3 = rb[9]*c2.y + rb[10]*c2.z + rb[11]*c2.w;
            float C4 = rb[12]*c3.x + rb[13]*c3.y + rb[14]*c3.z;
            float Q2 = rb[9]*c1.z + rb[10]*c1.w + rb[11]*c2.x;
            float Q3 = rb[6]*c2.y + rb[7]*c2.z + rb[8]*c2.w;
            float t014 = C0 + C1 + C4;
            float dotG2 = t014 + C2 + C3;
            float dotS2 = t014 + Q2 + Q3;
            float base2 = rb[15] + c3.w;
            float dgA1 = fmaxf(fmaf(-2.0f, dotG2, base2), 0.0f);
            float dgB1 = fmaxf(fmaf(-2.0f, dotS2, base2), 0.0f);
            if (dgA1 < m1b){ m1b=dgA1; i1b=mbase+jj; }
            if (dgB1 < m2b){ m2b=dgB1; i2b=mbase+jj; }

            const float candA = posA ? fminf(dgA0,dgB0) : FINF;
            const float candB = posB ? fminf(dgA1,dgB1) : FINF;
            scand[tid][j] = fminf(candA, candB);
        }
        __syncthreads();

        // column-min: 2 threads per column over 128 thread-rows
        const int col  = tid & 63;
        const int half = tid >> 6;
        float cm = scand[half*64][col];
        #pragma unroll 8
        for (int i=1;i<64;i++) cm = fminf(cm, scand[half*64+i][col]);
        scolpart[tid] = cm;
        __syncthreads();
        if (tid < 64)
            g_colmin[ntile][b*NN + mbase + jbase + tid] =
                fminf(scolpart[tid], scolpart[tid+64]);
        __syncthreads();
    }

    g_pm1[split][gA]=m1a; g_pi1[split][gA]=i1a;
    g_pm2[split][gA]=m2a; g_pi2[split][gA]=i2a;
    g_pm1[split][gB]=m1b; g_pi1[split][gB]=i1b;
    g_pm2[split][gB]=m2b; g_pi2[split][gB]=i2b;
}

// ---------------- Kernel C1: grid-parallel per-point epilogue -----------------
__global__ void kC1(const float* __restrict__ bsp, const float* __restrict__ succ_)
{
    __shared__ float red[256];
    const int tid = threadIdx.x;
    const int g   = blockIdx.x*256 + tid;   // 32 blocks x 256 = 8192
    const int b   = g >> 11;

    const float succ = succ_[g];
    const float cd = g_cd[g], ca = g_ca[g], off = g_off[g], sbce = g_sbce[g];

    // pred->gt best: merge NTILES column partials (min, order-free); always finite
    float best = g_colmin[0][g];
    #pragma unroll
    for (int t=1;t<NTILES;t++) best = fminf(best, g_colmin[t][g]);
    const float adds = bsp[g]*sqrtf(best);   // gate applied per-batch in kC2

    // gt->pred: ordered merge of MSPLIT partials (first-occurrence argmin)
    float m1=g_pm1[0][g]; int i1=g_pi1[0][g];
    float m2=g_pm2[0][g]; int i2=g_pi2[0][g];
    #pragma unroll
    for (int s=1;s<MSPLIT;s++){
        const float a=g_pm1[s][g]; if (a<m1){m1=a;i1=g_pi1[s][g];}
        const float c=g_pm2[s][g]; if (c<m2){m2=c;i2=g_pi2[s][g];}
    }
    const int idcs = (m2<m1)? i2 : i1;
    const float conf = bsp[b*NN+idcs];
    const float g2p = conf * fminf(m1,m2) * succ;

    float vals[7] = {cd, ca, off, g2p, adds, succ, sbce};
    #pragma unroll
    for (int q=0;q<7;q++){
        red[tid]=vals[q]; __syncthreads();
        for (int s=128;s>0;s>>=1){ if(tid<s) red[tid]+=red[tid+s]; __syncthreads(); }
        if (tid==0) g_part[blockIdx.x][q]=red[0];
        __syncthreads();
    }
}

// ---------------- Kernel C2: tiny deterministic merge -------------------------
__global__ void kC2(float* __restrict__ out)
{
    __shared__ float sp[32][8];
    const int t = threadIdx.x;
    if (t < 32){
        #pragma unroll
        for (int q=0;q<7;q++) sp[t][q]=g_part[t][q];
    }
    __syncthreads();
    if (t==0){
        float tdir=0.f,tapp=0.f,toff=0.f,tg2p=0.f,tadds=0.f,tsb=0.f;
        for (int b=0;b<BB;b++){
            float s[7]={0,0,0,0,0,0,0};
            for (int k=0;k<8;k++){           // 8 blocks per batch, fixed order
                #pragma unroll
                for (int q=0;q<7;q++) s[q]+=sp[b*8+k][q];
            }
            const float piv  = fmaxf(s[5],1.0f);
            const float gate = fminf(s[5],1.0f);
            tdir += s[0]/piv; tapp += s[1]/piv; toff += s[2]/piv;
            tg2p += s[3]/piv; tadds += gate*s[4]; tsb += s[6];
        }
        out[0] = tdir/(float)BB + tsb/(float)BN + toff/(float)BB + tapp/(float)BB
               + 10.0f*(tadds/(float)BN) + tg2p/(float)BB;
    }
}

// ---------------- launcher ---------------------------------------------------
extern "C" void kernel_launch(void* const* d_in, const int* in_sizes, int n_in,
                              void* d_out, int out_size)
{
    const float* gd   = (const float*)d_in[0];
    const float* ad   = (const float*)d_in[1];
    const float* oh   = (const float*)d_in[2];
    const float* pp   = (const float*)d_in[3];
    const float* bsp  = (const float*)d_in[4];
    const float* bsh  = (const float*)d_in[5];
    const float* dl   = (const float*)d_in[6];
    const float* ol   = (const float*)d_in[7];
    const float* succ = (const float*)d_in[8];
    const float* al   = (const float*)d_in[9];
    const float* bv   = (const float*)d_in[10];
    const float* bw   = (const float*)d_in[11];
    const float* cpt  = (const float*)d_in[12];
    const float* scpt = (const float*)d_in[13];
    float* out = (float*)d_out;

    kA<<<BN/128, 128>>>(gd, ad, oh, pp, bsh, dl, ol, succ, al, bv, bw, cpt, scpt);
    kB<<<dim3(NTILES, BB, MSPLIT), 128>>>(succ);
    kC1<<<32, 256>>>(bsp, succ);
    kC2<<<1, 32>>>(out);
}